// round 2
// baseline (speedup 1.0000x reference)
#include <cuda_runtime.h>
#include <math.h>

#define B_TOT 4096
#define T_LEN 32
#define DDIM 15
#define NSTEPS 5
#define DT_C 0.2f

// ---------------- scratch (static device globals; no allocation) ----------------
__device__ float g_WihT[25 * 384];
__device__ float g_WhhT[128 * 384];
__device__ float g_projT[128 * 64];
__device__ float g_dr0T[89 * 128];
__device__ float g_dr1T[128 * 128];
__device__ float g_dr2T[128 * 128];
__device__ float g_dr3T[128 * 15];
__device__ float g_df0T[89 * 128];
__device__ float g_df1T[128 * 128];
__device__ float g_df2T[128 * 15];
__device__ float g_ctx[B_TOT * 64];

// ---------------- prep: transpose all weights for coalesced GEMV reads ----------
__global__ void prep_kernel(const float* __restrict__ wih, const float* __restrict__ whh,
                            const float* __restrict__ proj,
                            const float* __restrict__ d0, const float* __restrict__ d1,
                            const float* __restrict__ d2, const float* __restrict__ d3,
                            const float* __restrict__ f0, const float* __restrict__ f1,
                            const float* __restrict__ f2) {
    int tid = blockIdx.x * blockDim.x + threadIdx.x;
    int nt = gridDim.x * blockDim.x;
    for (int i = tid; i < 384 * 25; i += nt) { int o = i / 25, k = i - o * 25; g_WihT[k * 384 + o] = wih[i]; }
    for (int i = tid; i < 384 * 128; i += nt) { int o = i >> 7, k = i & 127; g_WhhT[k * 384 + o] = whh[i]; }
    for (int i = tid; i < 64 * 128; i += nt) { int o = i >> 7, k = i & 127; g_projT[k * 64 + o] = proj[i]; }
    for (int i = tid; i < 128 * 89; i += nt) { int o = i / 89, k = i - o * 89; g_dr0T[k * 128 + o] = d0[i]; }
    for (int i = tid; i < 128 * 128; i += nt) { int o = i >> 7, k = i & 127; g_dr1T[k * 128 + o] = d1[i]; }
    for (int i = tid; i < 128 * 128; i += nt) { int o = i >> 7, k = i & 127; g_dr2T[k * 128 + o] = d2[i]; }
    for (int i = tid; i < 15 * 128; i += nt) { int o = i >> 7, k = i & 127; g_dr3T[k * 15 + o] = d3[i]; }
    for (int i = tid; i < 128 * 89; i += nt) { int o = i / 89, k = i - o * 89; g_df0T[k * 128 + o] = f0[i]; }
    for (int i = tid; i < 128 * 128; i += nt) { int o = i >> 7, k = i & 127; g_df1T[k * 128 + o] = f1[i]; }
    for (int i = tid; i < 15 * 128; i += nt) { int o = i >> 7, k = i & 127; g_df2T[k * 15 + o] = f2[i]; }
}

// ---------------- GRU encoder: 128 blocks x 256 threads, 32 batch rows/block ----
__global__ void __launch_bounds__(256) gru_kernel(const float* __restrict__ C,
                                                  const float* __restrict__ bias,
                                                  const float* __restrict__ bias_n,
                                                  const float* __restrict__ proj_b) {
    __shared__ float h_s[32][128];
    __shared__ float x_s[32][25];
    const int tid = threadIdx.x;
    const int b0 = blockIdx.x * 32;
    const int j = tid & 127, rg = tid >> 7, rbase = rg * 16;

    for (int i = tid; i < 32 * 128; i += 256) ((float*)h_s)[i] = 0.f;
    const float br = bias[j], bz = bias[128 + j], bg = bias[256 + j], bn = bias_n[j];

    for (int t = 0; t < T_LEN; t++) {
        __syncthreads();
        for (int i = tid; i < 800; i += 256) {
            int r = i / 25, k = i - r * 25;
            int ii = k / 5, jj = k - ii * 5;
            const float* p = C + ((size_t)(b0 + r) * T_LEN + t) * 25;
            x_s[r][k] = 0.5f * (p[ii * 5 + jj] + p[jj * 5 + ii]);
        }
        __syncthreads();

        float a_r[16], a_z[16], a_g[16], a_h[16];
#pragma unroll
        for (int m = 0; m < 16; m++) { a_r[m] = br; a_z[m] = bz; a_g[m] = bg; a_h[m] = 0.f; }

        // input part: gi = x @ Wih^T + b
#pragma unroll 5
        for (int k = 0; k < 25; k++) {
            float wr = g_WihT[k * 384 + j];
            float wz = g_WihT[k * 384 + 128 + j];
            float wg = g_WihT[k * 384 + 256 + j];
#pragma unroll
            for (int m = 0; m < 16; m++) {
                float xv = x_s[rbase + m][k];
                a_r[m] += wr * xv; a_z[m] += wz * xv; a_g[m] += wg * xv;
            }
        }
        // hidden part: gh = h @ Whh^T
#pragma unroll 4
        for (int k = 0; k < 128; k++) {
            float wr = g_WhhT[k * 384 + j];
            float wz = g_WhhT[k * 384 + 128 + j];
            float wg = g_WhhT[k * 384 + 256 + j];
#pragma unroll
            for (int m = 0; m < 16; m++) {
                float hv = h_s[rbase + m][k];
                a_r[m] += wr * hv; a_z[m] += wz * hv; a_h[m] += wg * hv;
            }
        }

        float hnew[16];
#pragma unroll
        for (int m = 0; m < 16; m++) {
            float r = 1.f / (1.f + __expf(-a_r[m]));
            float z = 1.f / (1.f + __expf(-a_z[m]));
            float g = tanhf(a_g[m] + r * (a_h[m] + bn));
            hnew[m] = (1.f - z) * g + z * h_s[rbase + m][j];
        }
        __syncthreads();
#pragma unroll
        for (int m = 0; m < 16; m++) h_s[rbase + m][j] = hnew[m];
    }
    __syncthreads();

    // ctx = hT @ proj_w^T + proj_b   (32 rows x 64 cols)
    {
        const int jc = tid & 63, rg2 = tid >> 6;
        const float pb = proj_b[jc];
#pragma unroll
        for (int m = 0; m < 8; m++) {
            int r = rg2 * 8 + m;
            float acc = pb;
#pragma unroll 4
            for (int k = 0; k < 128; k++) acc += h_s[r][k] * g_projT[k * 64 + jc];
            g_ctx[(size_t)(b0 + r) * 64 + jc] = acc;
        }
    }
}

// ---------------- 5x5 helpers (all unrolled -> registers) ------------------------
__device__ __forceinline__ void mm5(const float* A, const float* Bm, float* Cm) {
#pragma unroll
    for (int i = 0; i < 5; i++) {
#pragma unroll
        for (int jj = 0; jj < 5; jj++) {
            float s = A[i * 5] * Bm[jj];
#pragma unroll
            for (int k = 1; k < 5; k++) s += A[i * 5 + k] * Bm[k * 5 + jj];
            Cm[i * 5 + jj] = s;
        }
    }
}

// one SDE geometric update for one batch element; row = inp_s row
// row[0..24] = sigma (symmetric), row[89..103] = coeff (tangent coords)
__device__ void geo_update(float* row) {
    const float is2 = 0.70710678118654752f;
    float S[25];
#pragma unroll
    for (int i = 0; i < 25; i++) S[i] = row[i];
    float c[15];
#pragma unroll
    for (int i = 0; i < 15; i++) c[i] = row[89 + i];

    // a = sum_k coeff_k * B_k  (orthonormal symmetric basis)
    float A[25];
    A[0] = c[0]; A[6] = c[1]; A[12] = c[2]; A[18] = c[3]; A[24] = c[4];
    A[1] = A[5] = c[5] * is2;   A[2] = A[10] = c[6] * is2;
    A[3] = A[15] = c[7] * is2;  A[4] = A[20] = c[8] * is2;
    A[7] = A[11] = c[9] * is2;  A[8] = A[16] = c[10] * is2;
    A[9] = A[21] = c[11] * is2; A[13] = A[17] = c[12] * is2;
    A[14] = A[22] = c[13] * is2; A[19] = A[23] = c[14] * is2;

    // L = sqrtm(S) via coupled Newton-Schulz (eigenvalues of S/tr in (0,1])
    float tr = S[0] + S[6] + S[12] + S[18] + S[24];
    float ia = 1.0f / tr;
    float Y[25], Z[25];
#pragma unroll
    for (int i = 0; i < 25; i++) { Y[i] = S[i] * ia; Z[i] = 0.f; }
    Z[0] = Z[6] = Z[12] = Z[18] = Z[24] = 1.f;
    for (int it = 0; it < 16; it++) {
        float P[25]; mm5(Z, Y, P);
        float Tm[25];
#pragma unroll
        for (int i = 0; i < 25; i++) Tm[i] = -0.5f * P[i];
        Tm[0] += 1.5f; Tm[6] += 1.5f; Tm[12] += 1.5f; Tm[18] += 1.5f; Tm[24] += 1.5f;
        float Yn[25], Zn[25];
        mm5(Y, Tm, Yn); mm5(Tm, Z, Zn);
#pragma unroll
        for (int i = 0; i < 25; i++) { Y[i] = Yn[i]; Z[i] = Zn[i]; }
    }
    float sa = sqrtf(tr);
    float L[25];
#pragma unroll
    for (int i = 0; i < 25; i++) L[i] = Y[i] * sa;

    // E = expm(A), 12-term Horner Taylor (||A|| << 1)
    float E[25];
#pragma unroll
    for (int i = 0; i < 25; i++) E[i] = 0.f;
    E[0] = E[6] = E[12] = E[18] = E[24] = 1.f;
#pragma unroll
    for (int k = 12; k >= 1; k--) {
        float AE[25]; mm5(A, E, AE);
        const float invk = 1.0f / (float)k;
#pragma unroll
        for (int i = 0; i < 25; i++) E[i] = AE[i] * invk;
        E[0] += 1.f; E[6] += 1.f; E[12] += 1.f; E[18] += 1.f; E[24] += 1.f;
    }

    // sigma_new = sym(L E L)
    float M1[25], M2[25];
    mm5(L, E, M1); mm5(M1, L, M2);
#pragma unroll
    for (int i = 0; i < 5; i++)
#pragma unroll
        for (int jj = 0; jj < 5; jj++)
            row[i * 5 + jj] = 0.5f * (M2[i * 5 + jj] + M2[jj * 5 + i]);
}

// ---------------- SDE kernel: 128 blocks x 256 threads, 32 elements/block -------
__global__ void __launch_bounds__(256) sde_kernel(
    const float* __restrict__ C, const float* __restrict__ dW,
    const float* __restrict__ db0, const float* __restrict__ db1,
    const float* __restrict__ db2, const float* __restrict__ db3,
    const float* __restrict__ fb0, const float* __restrict__ fb1,
    const float* __restrict__ fb2, float* __restrict__ out) {
    __shared__ float inp_s[32][104];   // [0..24]=sigma, [25..88]=ctx, [89..103]=drift/coeff
    __shared__ float b1_s[32][128];
    __shared__ float b2_s[32][128];
    const int tid = threadIdx.x;
    const int b0 = blockIdx.x * 32;
    const int j = tid & 127, rg = tid >> 7, rbase = rg * 16;

    const float v_db0 = db0[j], v_db1 = db1[j], v_db2 = db2[j];
    const float v_fb0 = fb0[j], v_fb1 = fb1[j];

    // init: ctx and sigma_0 = sym(context_spd[:, T-1])
    for (int i = tid; i < 32 * 64; i += 256) {
        int r = i >> 6, k = i & 63;
        inp_s[r][25 + k] = g_ctx[(size_t)(b0 + r) * 64 + k];
    }
    for (int i = tid; i < 800; i += 256) {
        int r = i / 25, k = i - r * 25;
        int ii = k / 5, jj = k - ii * 5;
        const float* p = C + ((size_t)(b0 + r) * T_LEN + (T_LEN - 1)) * 25;
        inp_s[r][k] = 0.5f * (p[ii * 5 + jj] + p[jj * 5 + ii]);
    }
    __syncthreads();

    for (int step = 0; step < NSTEPS; step++) {
        // drift L0: b1 = silu(inp @ W0^T + b0)
        {
            float acc[16];
#pragma unroll
            for (int m = 0; m < 16; m++) acc[m] = v_db0;
#pragma unroll 4
            for (int k = 0; k < 89; k++) {
                float w = g_dr0T[k * 128 + j];
#pragma unroll
                for (int m = 0; m < 16; m++) acc[m] += inp_s[rbase + m][k] * w;
            }
#pragma unroll
            for (int m = 0; m < 16; m++) { float x = acc[m]; b1_s[rbase + m][j] = x / (1.f + __expf(-x)); }
        }
        __syncthreads();
        // drift L1: b2 = silu(b1 @ W1^T + b1d)
        {
            float acc[16];
#pragma unroll
            for (int m = 0; m < 16; m++) acc[m] = v_db1;
#pragma unroll 4
            for (int k = 0; k < 128; k++) {
                float w = g_dr1T[k * 128 + j];
#pragma unroll
                for (int m = 0; m < 16; m++) acc[m] += b1_s[rbase + m][k] * w;
            }
#pragma unroll
            for (int m = 0; m < 16; m++) { float x = acc[m]; b2_s[rbase + m][j] = x / (1.f + __expf(-x)); }
        }
        __syncthreads();
        // drift L2: b1 = silu(b2 @ W2^T + b2d)
        {
            float acc[16];
#pragma unroll
            for (int m = 0; m < 16; m++) acc[m] = v_db2;
#pragma unroll 4
            for (int k = 0; k < 128; k++) {
                float w = g_dr2T[k * 128 + j];
#pragma unroll
                for (int m = 0; m < 16; m++) acc[m] += b2_s[rbase + m][k] * w;
            }
#pragma unroll
            for (int m = 0; m < 16; m++) { float x = acc[m]; b1_s[rbase + m][j] = x / (1.f + __expf(-x)); }
        }
        __syncthreads();
        // drift L3 (480 work items, strided over 256 threads) + diff L0 (all threads)
        {
            for (int w480 = tid; w480 < 480; w480 += 256) {
                int r = w480 / 15, k = w480 - r * 15;
                float acc = db3[k];
#pragma unroll 4
                for (int cc = 0; cc < 128; cc++) acc += b1_s[r][cc] * g_dr3T[cc * 15 + k];
                inp_s[r][89 + k] = acc;   // raw drift_c
            }
            float acc[16];
#pragma unroll
            for (int m = 0; m < 16; m++) acc[m] = v_fb0;
#pragma unroll 4
            for (int k = 0; k < 89; k++) {
                float w = g_df0T[k * 128 + j];
#pragma unroll
                for (int m = 0; m < 16; m++) acc[m] += inp_s[rbase + m][k] * w;
            }
#pragma unroll
            for (int m = 0; m < 16; m++) { float x = acc[m]; b2_s[rbase + m][j] = x / (1.f + __expf(-x)); }
        }
        __syncthreads();
        // diff L1: b1 = silu(b2 @ dW1^T + fb1)
        {
            float acc[16];
#pragma unroll
            for (int m = 0; m < 16; m++) acc[m] = v_fb1;
#pragma unroll 4
            for (int k = 0; k < 128; k++) {
                float w = g_df1T[k * 128 + j];
#pragma unroll
                for (int m = 0; m < 16; m++) acc[m] += b2_s[rbase + m][k] * w;
            }
#pragma unroll
            for (int m = 0; m < 16; m++) { float x = acc[m]; b1_s[rbase + m][j] = x / (1.f + __expf(-x)); }
        }
        __syncthreads();
        // diff L2 + combine: coeff = drift*DT + softplus(.)*dW   (480 items, strided)
        for (int w480 = tid; w480 < 480; w480 += 256) {
            int r = w480 / 15, k = w480 - r * 15;
            float acc = fb2[k];
#pragma unroll 4
            for (int cc = 0; cc < 128; cc++) acc += b1_s[r][cc] * g_df2T[cc * 15 + k];
            float sp = (acc > 20.f) ? acc : log1pf(__expf(acc));
            float dwv = dW[((size_t)(b0 + r) * NSTEPS + step) * DDIM + k];
            inp_s[r][89 + k] = inp_s[r][89 + k] * DT_C + sp * dwv;
        }
        __syncthreads();
        // geometric update: one element per lane of warp 0
        if (tid < 32) geo_update(&inp_s[tid][0]);
        __syncthreads();
    }

    for (int i = tid; i < 800; i += 256) {
        int r = i / 25, k = i - r * 25;
        out[(size_t)(b0 + r) * 25 + k] = inp_s[r][k];
    }
}

// ---------------- launch ---------------------------------------------------------
extern "C" void kernel_launch(void* const* d_in, const int* in_sizes, int n_in,
                              void* d_out, int out_size) {
    const float* ctx_spd = (const float*)d_in[0];
    const float* dWp     = (const float*)d_in[1];
    const float* wih     = (const float*)d_in[2];
    const float* whh     = (const float*)d_in[3];
    const float* gbias   = (const float*)d_in[4];
    const float* gbias_n = (const float*)d_in[5];
    const float* projw   = (const float*)d_in[6];
    const float* projb   = (const float*)d_in[7];
    const float* dw0 = (const float*)d_in[8];  const float* db0 = (const float*)d_in[9];
    const float* dw1 = (const float*)d_in[10]; const float* db1 = (const float*)d_in[11];
    const float* dw2 = (const float*)d_in[12]; const float* db2 = (const float*)d_in[13];
    const float* dw3 = (const float*)d_in[14]; const float* db3 = (const float*)d_in[15];
    const float* fw0 = (const float*)d_in[16]; const float* fb0 = (const float*)d_in[17];
    const float* fw1 = (const float*)d_in[18]; const float* fb1 = (const float*)d_in[19];
    const float* fw2 = (const float*)d_in[20]; const float* fb2 = (const float*)d_in[21];
    float* out = (float*)d_out;

    prep_kernel<<<64, 256>>>(wih, whh, projw, dw0, dw1, dw2, dw3, fw0, fw1, fw2);
    gru_kernel<<<128, 256>>>(ctx_spd, gbias, gbias_n, projb);
    sde_kernel<<<128, 256>>>(ctx_spd, dWp, db0, db1, db2, db3, fb0, fb1, fb2, out);
}